// round 3
// baseline (speedup 1.0000x reference)
#include <cuda_runtime.h>

#define Bn 16
#define Cc 256
#define Sn 4096   // H*W
#define C8 32     // C/8
#define C2 128    // C/2
#define Dn 1024   // down = HW/4

typedef unsigned long long ull;

// ---- packed fp32x2 helpers (sm_103a FFMA2 path) ----
__device__ __forceinline__ ull ffma2(ull a, ull b, ull c) {
    ull d;
    asm("fma.rn.f32x2 %0, %1, %2, %3;" : "=l"(d) : "l"(a), "l"(b), "l"(c));
    return d;
}
__device__ __forceinline__ ull dup2(float v) {
    ull d;
    asm("mov.b64 %0, {%1, %1};" : "=l"(d) : "f"(v));
    return d;
}
__device__ __forceinline__ float2 upk(ull v) {
    float2 r;
    asm("mov.b64 {%0, %1}, %2;" : "=f"(r.x), "=f"(r.y) : "l"(v));
    return r;
}

// ---- scratch (device globals; no allocation allowed) ----
__device__ float g_q[(size_t)Bn * C8 * Sn];
__device__ float g_k[(size_t)Bn * C8 * Dn];
__device__ float g_v[(size_t)Bn * C2 * Dn];
__device__ float g_attn[(size_t)Bn * Sn * Dn];  // 268MB logits -> normalized weights
__device__ float g_app[(size_t)Bn * Sn * C2];

// ---------------------------------------------------------------------------
// Fused conv: q (32ch full res), k (32ch pooled), v (128ch pooled) as one
// GEMM Y[192,4096] = W[192,256] * X[256,4096] per batch, pooled epilogue.
// grid (32, 3, Bn), block 128, micro 8x8 f32x2.
// ---------------------------------------------------------------------------
__global__ __launch_bounds__(128) void conv_all_k(
    const float* __restrict__ x,
    const float* __restrict__ qw, const float* __restrict__ qb,
    const float* __restrict__ kw, const float* __restrict__ kb,
    const float* __restrict__ vw, const float* __restrict__ vb) {
    int b = blockIdx.z, ot = blockIdx.y, st = blockIdx.x;
    int s0 = st * 128;
    int t = threadIdx.x;

    __shared__ __align__(16) union {
        struct { float Ws[2][16][68]; float Xs[2][16][128]; } p;
        float Cs[64][128];
    } sm;

    int wrow = t >> 1;
    int wkg = (t & 1) << 3;
    int gch = ot * 64 + wrow;
    const float* wsrc;
    if (gch < 32) wsrc = qw + (size_t)gch * Cc;
    else if (gch < 64) wsrc = kw + (size_t)(gch - 32) * Cc;
    else wsrc = vw + (size_t)(gch - 64) * Cc;
    wsrc += wkg;

    int xkk = t >> 3;
    int xsg = (t & 7) << 4;
    const float* xsrc = x + (size_t)b * Cc * Sn + (size_t)xkk * Sn + s0 + xsg;

    int ty = t >> 4, tx = t & 15;

    ull acc[8][4];
#pragma unroll
    for (int i = 0; i < 8; i++)
#pragma unroll
        for (int j = 0; j < 4; j++) acc[i][j] = 0ULL;

    {
#pragma unroll
        for (int u = 0; u < 2; u++) {
            float4 v = *(const float4*)(wsrc + u * 4);
            sm.p.Ws[0][wkg + u * 4 + 0][wrow] = v.x;
            sm.p.Ws[0][wkg + u * 4 + 1][wrow] = v.y;
            sm.p.Ws[0][wkg + u * 4 + 2][wrow] = v.z;
            sm.p.Ws[0][wkg + u * 4 + 3][wrow] = v.w;
        }
#pragma unroll
        for (int u = 0; u < 4; u++)
            *(float4*)&sm.p.Xs[0][xkk][xsg + u * 4] = *(const float4*)(xsrc + u * 4);
    }
    __syncthreads();

    for (int ch = 0; ch < 16; ch++) {
        int cb = ch & 1;
        float4 wpre[2], xpre[4];
        if (ch < 15) {
            const float* wp = wsrc + (ch + 1) * 16;
            wpre[0] = *(const float4*)(wp);
            wpre[1] = *(const float4*)(wp + 4);
            const float* xp = xsrc + (size_t)(ch + 1) * 16 * Sn;
#pragma unroll
            for (int u = 0; u < 4; u++) xpre[u] = *(const float4*)(xp + u * 4);
        }
#pragma unroll
        for (int kk = 0; kk < 16; kk++) {
            float4 a0 = *(const float4*)&sm.p.Ws[cb][kk][ty * 8];
            float4 a1 = *(const float4*)&sm.p.Ws[cb][kk][ty * 8 + 4];
            ulonglong2 b0 = *(const ulonglong2*)&sm.p.Xs[cb][kk][tx * 8];
            ulonglong2 b1 = *(const ulonglong2*)&sm.p.Xs[cb][kk][tx * 8 + 4];
            ull bp[4] = {b0.x, b0.y, b1.x, b1.y};
            float aa[8] = {a0.x, a0.y, a0.z, a0.w, a1.x, a1.y, a1.z, a1.w};
#pragma unroll
            for (int i = 0; i < 8; i++) {
                ull ad = dup2(aa[i]);
#pragma unroll
                for (int j = 0; j < 4; j++) acc[i][j] = ffma2(ad, bp[j], acc[i][j]);
            }
        }
        if (ch < 15) {
            int nb = cb ^ 1;
#pragma unroll
            for (int u = 0; u < 2; u++) {
                sm.p.Ws[nb][wkg + u * 4 + 0][wrow] = (&wpre[u].x)[0];
                sm.p.Ws[nb][wkg + u * 4 + 1][wrow] = (&wpre[u].x)[1];
                sm.p.Ws[nb][wkg + u * 4 + 2][wrow] = (&wpre[u].x)[2];
                sm.p.Ws[nb][wkg + u * 4 + 3][wrow] = (&wpre[u].x)[3];
            }
#pragma unroll
            for (int u = 0; u < 4; u++)
                *(float4*)&sm.p.Xs[nb][xkk][xsg + u * 4] = xpre[u];
        }
        __syncthreads();
    }

#pragma unroll
    for (int i = 0; i < 8; i++) {
        ulonglong2 u0, u1;
        u0.x = acc[i][0]; u0.y = acc[i][1];
        u1.x = acc[i][2]; u1.y = acc[i][3];
        *(ulonglong2*)&sm.Cs[ty * 8 + i][tx * 8] = u0;
        *(ulonglong2*)&sm.Cs[ty * 8 + i][tx * 8 + 4] = u1;
    }
    __syncthreads();

    if (ot == 0) {
#pragma unroll
        for (int i = 0; i < 8; i++) {
            int o = i * 4 + (t >> 5);
            int sp = (t & 31) * 4;
            float4 v = *(const float4*)&sm.Cs[o][sp];
            float bb = qb[o];
            v.x += bb; v.y += bb; v.z += bb; v.w += bb;
            *(float4*)(g_q + (size_t)b * C8 * Sn + (size_t)o * Sn + s0 + sp) = v;
        }
        {
            int o = 32 + (t >> 2);
            int qcb = (t & 3) * 8;
            float bb = kb[o - 32];
            float* dst = g_k + (size_t)b * C8 * Dn + (size_t)(o - 32) * Dn + st * 32;
#pragma unroll
            for (int jj = 0; jj < 8; jj++) {
                int qc = qcb + jj;
                float m = fmaxf(fmaxf(sm.Cs[o][2 * qc], sm.Cs[o][2 * qc + 1]),
                                fmaxf(sm.Cs[o][64 + 2 * qc], sm.Cs[o][64 + 2 * qc + 1]));
                dst[qc] = m + bb;
            }
        }
    } else {
        int vg0 = (ot - 1) * 64;
        int o = t >> 1;
        int qcb = (t & 1) * 16;
        float bb = vb[vg0 + o];
        float* dst = g_v + (size_t)b * C2 * Dn + (size_t)(vg0 + o) * Dn + st * 32;
#pragma unroll
        for (int jj = 0; jj < 16; jj++) {
            int qc = qcb + jj;
            float m = fmaxf(fmaxf(sm.Cs[o][2 * qc], sm.Cs[o][2 * qc + 1]),
                            fmaxf(sm.Cs[o][64 + 2 * qc], sm.Cs[o][64 + 2 * qc + 1]));
            dst[qc] = m + bb;
        }
    }
}

// ---------------------------------------------------------------------------
// attn logits: attn[b,l,j] = dot(qflat[l*32..], kflat[j*32..], 32)
// tile 128x128, 256 threads, micro 8x8 f32x2, K=32 one-shot.
// ---------------------------------------------------------------------------
__global__ __launch_bounds__(256, 2) void attn_gemm_k() {
    int b = blockIdx.z, l0 = blockIdx.y * 128, j0 = blockIdx.x * 128;
    __shared__ __align__(16) float As[32][132];
    __shared__ __align__(16) float Bs[32][128];
    int t = threadIdx.x;
    int row = t >> 1, kg = (t & 1) * 16;
    const float* ar = g_q + (size_t)b * C8 * Sn + (size_t)(l0 + row) * 32 + kg;
    const float* br = g_k + (size_t)b * C8 * Dn + (size_t)(j0 + row) * 32 + kg;
#pragma unroll
    for (int u = 0; u < 4; u++) {
        float4 v = *(const float4*)(ar + u * 4);
        As[kg + u * 4 + 0][row] = v.x;
        As[kg + u * 4 + 1][row] = v.y;
        As[kg + u * 4 + 2][row] = v.z;
        As[kg + u * 4 + 3][row] = v.w;
        float4 w = *(const float4*)(br + u * 4);
        Bs[kg + u * 4 + 0][row] = w.x;
        Bs[kg + u * 4 + 1][row] = w.y;
        Bs[kg + u * 4 + 2][row] = w.z;
        Bs[kg + u * 4 + 3][row] = w.w;
    }
    __syncthreads();

    int ty = t >> 4, tx = t & 15;
    ull acc[8][4];
#pragma unroll
    for (int i = 0; i < 8; i++)
#pragma unroll
        for (int j = 0; j < 4; j++) acc[i][j] = 0ULL;

#pragma unroll
    for (int kk = 0; kk < 32; kk++) {
        float4 a0 = *(const float4*)&As[kk][ty * 8];
        float4 a1 = *(const float4*)&As[kk][ty * 8 + 4];
        ulonglong2 b0 = *(const ulonglong2*)&Bs[kk][tx * 8];
        ulonglong2 b1 = *(const ulonglong2*)&Bs[kk][tx * 8 + 4];
        ull bp[4] = {b0.x, b0.y, b1.x, b1.y};
        float aa[8] = {a0.x, a0.y, a0.z, a0.w, a1.x, a1.y, a1.z, a1.w};
#pragma unroll
        for (int i = 0; i < 8; i++) {
            ull ad = dup2(aa[i]);
#pragma unroll
            for (int j = 0; j < 4; j++) acc[i][j] = ffma2(ad, bp[j], acc[i][j]);
        }
    }

#pragma unroll
    for (int i = 0; i < 8; i++) {
        float* cr = g_attn + (size_t)b * Sn * Dn + (size_t)(l0 + ty * 8 + i) * Dn + j0 + tx * 8;
        ulonglong2 u0, u1;
        u0.x = acc[i][0]; u0.y = acc[i][1];
        u1.x = acc[i][2]; u1.y = acc[i][3];
        *(ulonglong2*)cr = u0;
        *(ulonglong2*)(cr + 4) = u1;
    }
}

// ---------------------------------------------------------------------------
// Column softmax stats + in-place normalize.
// Pass1: per-column (b,j) max & sum over l. Pass2: a = exp(a-m)*(1/s).
// block (128,4): tx -> column, ty -> 1024-row chunk. grid (Dn/128, Bn)
// ---------------------------------------------------------------------------
__global__ void statsnorm_k() {
    int b = blockIdx.y;
    int tx = threadIdx.x;
    int ty = threadIdx.y;
    int j = blockIdx.x * 128 + tx;
    float* col = g_attn + (size_t)b * Sn * Dn + (size_t)ty * 1024 * Dn + j;

    float m = -1e30f, s = 0.f;
    for (int r = 0; r < 1024; r += 4) {
        float v0 = col[(size_t)(r + 0) * Dn];
        float v1 = col[(size_t)(r + 1) * Dn];
        float v2 = col[(size_t)(r + 2) * Dn];
        float v3 = col[(size_t)(r + 3) * Dn];
#define UPD(vv) { float mn_ = fmaxf(m, (vv)); s = fmaf(s, __expf(m - mn_), __expf((vv) - mn_)); m = mn_; }
        UPD(v0) UPD(v1) UPD(v2) UPD(v3)
#undef UPD
    }

    __shared__ float smx[4][128], ssum[4][128], fm[128], frs[128];
    smx[ty][tx] = m;
    ssum[ty][tx] = s;
    __syncthreads();
    if (ty == 0) {
#pragma unroll
        for (int tt = 1; tt < 4; tt++) {
            float m2 = smx[tt][tx], s2 = ssum[tt][tx];
            float mn = fmaxf(m, m2);
            s = s * __expf(m - mn) + s2 * __expf(m2 - mn);
            m = mn;
        }
        fm[tx] = m;
        frs[tx] = 1.f / s;
    }
    __syncthreads();
    float M = fm[tx], R = frs[tx];

    for (int r = 0; r < 1024; r += 4) {
        float* p0 = col + (size_t)(r + 0) * Dn;
        float* p1 = col + (size_t)(r + 1) * Dn;
        float* p2 = col + (size_t)(r + 2) * Dn;
        float* p3 = col + (size_t)(r + 3) * Dn;
        float v0 = *p0, v1 = *p1, v2 = *p2, v3 = *p3;
        *p0 = __expf(v0 - M) * R;
        *p1 = __expf(v1 - M) * R;
        *p2 = __expf(v2 - M) * R;
        *p3 = __expf(v3 - M) * R;
    }
}

// ---------------------------------------------------------------------------
// applied GEMM (pure): app[4096,128] = attnW[4096,1024] x v[1024,128]
// tile 128x128, 256 threads, micro 8x8 f32x2, K chunks of 16, dbl-buffered.
// __launch_bounds__(256,2) -> <=128 regs -> 2 CTAs/SM.
// grid (Sn/128, Bn)
// ---------------------------------------------------------------------------
__global__ __launch_bounds__(256, 2) void applied_gemm_k() {
    int b = blockIdx.y, l0 = blockIdx.x * 128;
    __shared__ __align__(16) float As[2][16][132];
    __shared__ __align__(16) float Bs[2][16][128];
    int t = threadIdx.x;

    int arow = t >> 1, akg = (t & 1) * 8;
    const float* asrc = g_attn + (size_t)b * Sn * Dn + (size_t)(l0 + arow) * Dn + akg;
    int bkk = t >> 4, bcg = (t & 15) * 8;
    const float* bsrc = g_v + (size_t)b * C2 * Dn + (size_t)bkk * C2 + bcg;

    int ty = t >> 4, tx = t & 15;
    ull acc[8][4];
#pragma unroll
    for (int i = 0; i < 8; i++)
#pragma unroll
        for (int j = 0; j < 4; j++) acc[i][j] = 0ULL;

    {
        float4 a0 = *(const float4*)(asrc);
        float4 a1 = *(const float4*)(asrc + 4);
        As[0][akg + 0][arow] = a0.x; As[0][akg + 1][arow] = a0.y;
        As[0][akg + 2][arow] = a0.z; As[0][akg + 3][arow] = a0.w;
        As[0][akg + 4][arow] = a1.x; As[0][akg + 5][arow] = a1.y;
        As[0][akg + 6][arow] = a1.z; As[0][akg + 7][arow] = a1.w;
        *(float4*)&Bs[0][bkk][bcg] = *(const float4*)(bsrc);
        *(float4*)&Bs[0][bkk][bcg + 4] = *(const float4*)(bsrc + 4);
    }
    __syncthreads();

    for (int ch = 0; ch < 64; ch++) {
        int cb = ch & 1;
        float4 pa0, pa1, pb0, pb1;
        if (ch < 63) {
            const float* ap = asrc + (ch + 1) * 16;
            pa0 = *(const float4*)(ap);
            pa1 = *(const float4*)(ap + 4);
            const float* bp2 = bsrc + (size_t)(ch + 1) * 16 * C2;
            pb0 = *(const float4*)(bp2);
            pb1 = *(const float4*)(bp2 + 4);
        }
#pragma unroll
        for (int kk = 0; kk < 16; kk++) {
            float4 a0 = *(const float4*)&As[cb][kk][ty * 8];
            float4 a1 = *(const float4*)&As[cb][kk][ty * 8 + 4];
            ulonglong2 b0 = *(const ulonglong2*)&Bs[cb][kk][tx * 8];
            ulonglong2 b1 = *(const ulonglong2*)&Bs[cb][kk][tx * 8 + 4];
            ull bp[4] = {b0.x, b0.y, b1.x, b1.y};
            float aa[8] = {a0.x, a0.y, a0.z, a0.w, a1.x, a1.y, a1.z, a1.w};
#pragma unroll
            for (int i = 0; i < 8; i++) {
                ull ad = dup2(aa[i]);
#pragma unroll
                for (int j = 0; j < 4; j++) acc[i][j] = ffma2(ad, bp[j], acc[i][j]);
            }
        }
        if (ch < 63) {
            int nb = cb ^ 1;
            As[nb][akg + 0][arow] = pa0.x; As[nb][akg + 1][arow] = pa0.y;
            As[nb][akg + 2][arow] = pa0.z; As[nb][akg + 3][arow] = pa0.w;
            As[nb][akg + 4][arow] = pa1.x; As[nb][akg + 5][arow] = pa1.y;
            As[nb][akg + 6][arow] = pa1.z; As[nb][akg + 7][arow] = pa1.w;
            *(float4*)&Bs[nb][bkk][bcg] = pb0;
            *(float4*)&Bs[nb][bkk][bcg + 4] = pb1;
        }
        __syncthreads();
    }

#pragma unroll
    for (int i = 0; i < 8; i++) {
        float* orow = g_app + (size_t)b * Sn * C2 + (size_t)(l0 + ty * 8 + i) * C2 + tx * 8;
        ulonglong2 u0, u1;
        u0.x = acc[i][0]; u0.y = acc[i][1];
        u1.x = acc[i][2]; u1.y = acc[i][3];
        *(ulonglong2*)orow = u0;
        *(ulonglong2*)(orow + 4) = u1;
    }
}

// ---------------------------------------------------------------------------
// output conv + residual: out = gamma*(W2[256,128] x appflat[128,4096] + b2) + x
// tile 128o x 128sp, 256 threads, micro 8x8 f32x2, K=128 chunks 16, dbl-buf.
// ---------------------------------------------------------------------------
__global__ __launch_bounds__(256, 2) void out_conv_k(
    const float* __restrict__ x, const float* __restrict__ w2,
    const float* __restrict__ b2, const float* __restrict__ gamma,
    float* __restrict__ out) {
    int b = blockIdx.z, o0 = blockIdx.y * 128, sp0 = blockIdx.x * 128;
    __shared__ __align__(16) float Ws[2][16][132];
    __shared__ __align__(16) float Bs[2][16][128];
    int t = threadIdx.x;

    int wrow = t >> 1, wkg = (t & 1) * 8;
    const float* wsrc = w2 + (size_t)(o0 + wrow) * C2 + wkg;
    int bkk = t >> 4, bsg = (t & 15) * 8;
    const float* asrc = g_app + (size_t)b * Sn * C2 + (size_t)bkk * Sn + sp0 + bsg;

    int ty = t >> 4, tx = t & 15;
    ull acc[8][4];
#pragma unroll
    for (int i = 0; i < 8; i++)
#pragma unroll
        for (int j = 0; j < 4; j++) acc[i][j] = 0ULL;

    {
        float4 w0 = *(const float4*)(wsrc);
        float4 w1 = *(const float4*)(wsrc + 4);
        Ws[0][wkg + 0][wrow] = w0.x; Ws[0][wkg + 1][wrow] = w0.y;
        Ws[0][wkg + 2][wrow] = w0.z; Ws[0][wkg + 3][wrow] = w0.w;
        Ws[0][wkg + 4][wrow] = w1.x; Ws[0][wkg + 5][wrow] = w1.y;
        Ws[0][wkg + 6][wrow] = w1.z; Ws[0][wkg + 7][wrow] = w1.w;
        *(float4*)&Bs[0][bkk][bsg] = *(const float4*)(asrc);
        *(float4*)&Bs[0][bkk][bsg + 4] = *(const float4*)(asrc + 4);
    }
    __syncthreads();

    for (int ch = 0; ch < 8; ch++) {
        int cb = ch & 1;
        float4 w0, w1, pb0, pb1;
        if (ch < 7) {
            int kc = (ch + 1) * 16;
            w0 = *(const float4*)(wsrc + kc);
            w1 = *(const float4*)(wsrc + kc + 4);
            const float* ap = asrc + (size_t)kc * Sn;
            pb0 = *(const float4*)(ap);
            pb1 = *(const float4*)(ap + 4);
        }
#pragma unroll
        for (int kk = 0; kk < 16; kk++) {
            float4 a0 = *(const float4*)&Ws[cb][kk][ty * 8];
            float4 a1 = *(const float4*)&Ws[cb][kk][ty * 8 + 4];
            ulonglong2 b0 = *(const ulonglong2*)&Bs[cb][kk][tx * 8];
            ulonglong2 b1 = *(const ulonglong2*)&Bs[cb][kk][tx * 8 + 4];
            ull bp[4] = {b0.x, b0.y, b1.x, b1.y};
            float aa[8] = {a0.x, a0.y, a0.z, a0.w, a1.x, a1.y, a1.z, a1.w};
#pragma unroll
            for (int i = 0; i < 8; i++) {
                ull ad = dup2(aa[i]);
#pragma unroll
                for (int j = 0; j < 4; j++) acc[i][j] = ffma2(ad, bp[j], acc[i][j]);
            }
        }
        if (ch < 7) {
            int nb = cb ^ 1;
            Ws[nb][wkg + 0][wrow] = w0.x; Ws[nb][wkg + 1][wrow] = w0.y;
            Ws[nb][wkg + 2][wrow] = w0.z; Ws[nb][wkg + 3][wrow] = w0.w;
            Ws[nb][wkg + 4][wrow] = w1.x; Ws[nb][wkg + 5][wrow] = w1.y;
            Ws[nb][wkg + 6][wrow] = w1.z; Ws[nb][wkg + 7][wrow] = w1.w;
            *(float4*)&Bs[nb][bkk][bsg] = pb0;
            *(float4*)&Bs[nb][bkk][bsg + 4] = pb1;
        }
        __syncthreads();
    }

    float g = gamma[0];
#pragma unroll
    for (int i = 0; i < 8; i++) {
        int o = o0 + ty * 8 + i;
        float bb = b2[o];
        const float* xr = x + (size_t)b * Cc * Sn + (size_t)o * Sn + sp0 + tx * 8;
        float* orow = out + (size_t)b * Cc * Sn + (size_t)o * Sn + sp0 + tx * 8;
        float2 v0 = upk(acc[i][0]), v1 = upk(acc[i][1]);
        float2 v2 = upk(acc[i][2]), v3 = upk(acc[i][3]);
        float4 xa = *(const float4*)(xr);
        float4 xb4 = *(const float4*)(xr + 4);
        float4 r0, r1;
        r0.x = fmaf(g, v0.x + bb, xa.x);
        r0.y = fmaf(g, v0.y + bb, xa.y);
        r0.z = fmaf(g, v1.x + bb, xa.z);
        r0.w = fmaf(g, v1.y + bb, xa.w);
        r1.x = fmaf(g, v2.x + bb, xb4.x);
        r1.y = fmaf(g, v2.y + bb, xb4.y);
        r1.z = fmaf(g, v3.x + bb, xb4.z);
        r1.w = fmaf(g, v3.y + bb, xb4.w);
        *(float4*)(orow) = r0;
        *(float4*)(orow + 4) = r1;
    }
}

// ---------------------------------------------------------------------------
extern "C" void kernel_launch(void* const* d_in, const int* in_sizes, int n_in,
                              void* d_out, int out_size) {
    const float* x   = (const float*)d_in[0];
    const float* qw  = (const float*)d_in[1];
    const float* qb  = (const float*)d_in[2];
    const float* kw  = (const float*)d_in[3];
    const float* kb  = (const float*)d_in[4];
    const float* vw  = (const float*)d_in[5];
    const float* vb  = (const float*)d_in[6];
    const float* v2w = (const float*)d_in[7];
    const float* v2b = (const float*)d_in[8];
    const float* gm  = (const float*)d_in[9];
    float* out = (float*)d_out;

    conv_all_k<<<dim3(32, 3, Bn), 128>>>(x, qw, qb, kw, kb, vw, vb);
    attn_gemm_k<<<dim3(Dn / 128, Sn / 128, Bn), 256>>>();
    statsnorm_k<<<dim3(Dn / 128, Bn), dim3(128, 4)>>>();
    applied_gemm_k<<<dim3(Sn / 128, Bn), 256>>>();
    out_conv_k<<<dim3(Sn / 128, 2, Bn), 256>>>(x, v2w, v2b, gm, out);
}

// round 5
// speedup vs baseline: 2.1215x; 2.1215x over previous
#include <cuda_runtime.h>
#include <cuda_bf16.h>
#include <cstdint>

#define Bn 16
#define Cc 256
#define Sn 4096   // H*W
#define C8 32     // C/8
#define C2 128    // C/2
#define Dn 1024   // down = HW/4

typedef unsigned long long ull;
typedef unsigned int uint;

// ---- packed fp32x2 helpers ----
__device__ __forceinline__ ull ffma2(ull a, ull b, ull c) {
    ull d;
    asm("fma.rn.f32x2 %0, %1, %2, %3;" : "=l"(d) : "l"(a), "l"(b), "l"(c));
    return d;
}
__device__ __forceinline__ ull dup2(float v) {
    ull d;
    asm("mov.b64 %0, {%1, %1};" : "=l"(d) : "f"(v));
    return d;
}
__device__ __forceinline__ float2 upk(ull v) {
    float2 r;
    asm("mov.b64 {%0, %1}, %2;" : "=f"(r.x), "=f"(r.y) : "l"(v));
    return r;
}

// ---- mma/ldmatrix helpers (baseline PTX, no 'a' target needed) ----
__device__ __forceinline__ uint32_t smem_u32(const void* p) {
    uint32_t a;
    asm("{ .reg .u64 t; cvta.to.shared.u64 t, %1; cvt.u32.u64 %0, t; }" : "=r"(a) : "l"(p));
    return a;
}
__device__ __forceinline__ void ldsm4(uint32_t a, uint& r0, uint& r1, uint& r2, uint& r3) {
    asm volatile("ldmatrix.sync.aligned.m8n8.x4.shared.b16 {%0,%1,%2,%3}, [%4];"
                 : "=r"(r0), "=r"(r1), "=r"(r2), "=r"(r3) : "r"(a));
}
__device__ __forceinline__ void ldsm4t(uint32_t a, uint& r0, uint& r1, uint& r2, uint& r3) {
    asm volatile("ldmatrix.sync.aligned.m8n8.x4.trans.shared.b16 {%0,%1,%2,%3}, [%4];"
                 : "=r"(r0), "=r"(r1), "=r"(r2), "=r"(r3) : "r"(a));
}
__device__ __forceinline__ void mma16816(float* d, uint a0, uint a1, uint a2, uint a3,
                                         uint b0, uint b1) {
    asm volatile(
        "mma.sync.aligned.m16n8k16.row.col.f32.bf16.bf16.f32 "
        "{%0,%1,%2,%3}, {%4,%5,%6,%7}, {%8,%9}, {%0,%1,%2,%3};"
        : "+f"(d[0]), "+f"(d[1]), "+f"(d[2]), "+f"(d[3])
        : "r"(a0), "r"(a1), "r"(a2), "r"(a3), "r"(b0), "r"(b1));
}

// split one fp32 into hi/lo bf16 pair
__device__ __forceinline__ void split2(float x, float y, uint& hi, uint& lo) {
    __nv_bfloat16 hx = __float2bfloat16_rn(x), hy = __float2bfloat16_rn(y);
    float rx = x - __bfloat162float(hx), ry = y - __bfloat162float(hy);
    __nv_bfloat16 lx = __float2bfloat16_rn(rx), ly = __float2bfloat16_rn(ry);
    __nv_bfloat162 hp, lp;
    hp.x = hx; hp.y = hy; lp.x = lx; lp.y = ly;
    hi = *(uint*)&hp;
    lo = *(uint*)&lp;
}

// ---- scratch ----
__device__ float g_q[(size_t)Bn * C8 * Sn];
__device__ float g_k[(size_t)Bn * C8 * Dn];
__device__ float g_v[(size_t)Bn * C2 * Dn];
__device__ float g_attn[(size_t)Bn * Sn * Dn];  // logits
__device__ float g_cmax[Bn * Dn];
__device__ float g_crs[Bn * Dn];
__device__ float g_app[(size_t)Bn * Sn * C2];

// ---------------------------------------------------------------------------
// Fused conv: q / k-pooled / v-pooled (unchanged, known-good 987us config)
// ---------------------------------------------------------------------------
__global__ __launch_bounds__(128) void conv_all_k(
    const float* __restrict__ x,
    const float* __restrict__ qw, const float* __restrict__ qb,
    const float* __restrict__ kw, const float* __restrict__ kb,
    const float* __restrict__ vw, const float* __restrict__ vb) {
    int b = blockIdx.z, ot = blockIdx.y, st = blockIdx.x;
    int s0 = st * 128;
    int t = threadIdx.x;

    __shared__ __align__(16) union {
        struct { float Ws[2][16][68]; float Xs[2][16][128]; } p;
        float Cs[64][128];
    } sm;

    int wrow = t >> 1;
    int wkg = (t & 1) << 3;
    int gch = ot * 64 + wrow;
    const float* wsrc;
    if (gch < 32) wsrc = qw + (size_t)gch * Cc;
    else if (gch < 64) wsrc = kw + (size_t)(gch - 32) * Cc;
    else wsrc = vw + (size_t)(gch - 64) * Cc;
    wsrc += wkg;

    int xkk = t >> 3;
    int xsg = (t & 7) << 4;
    const float* xsrc = x + (size_t)b * Cc * Sn + (size_t)xkk * Sn + s0 + xsg;

    int ty = t >> 4, tx = t & 15;

    ull acc[8][4];
#pragma unroll
    for (int i = 0; i < 8; i++)
#pragma unroll
        for (int j = 0; j < 4; j++) acc[i][j] = 0ULL;

    {
#pragma unroll
        for (int u = 0; u < 2; u++) {
            float4 v = *(const float4*)(wsrc + u * 4);
            sm.p.Ws[0][wkg + u * 4 + 0][wrow] = v.x;
            sm.p.Ws[0][wkg + u * 4 + 1][wrow] = v.y;
            sm.p.Ws[0][wkg + u * 4 + 2][wrow] = v.z;
            sm.p.Ws[0][wkg + u * 4 + 3][wrow] = v.w;
        }
#pragma unroll
        for (int u = 0; u < 4; u++)
            *(float4*)&sm.p.Xs[0][xkk][xsg + u * 4] = *(const float4*)(xsrc + u * 4);
    }
    __syncthreads();

    for (int ch = 0; ch < 16; ch++) {
        int cb = ch & 1;
        float4 wpre[2], xpre[4];
        if (ch < 15) {
            const float* wp = wsrc + (ch + 1) * 16;
            wpre[0] = *(const float4*)(wp);
            wpre[1] = *(const float4*)(wp + 4);
            const float* xp = xsrc + (size_t)(ch + 1) * 16 * Sn;
#pragma unroll
            for (int u = 0; u < 4; u++) xpre[u] = *(const float4*)(xp + u * 4);
        }
#pragma unroll
        for (int kk = 0; kk < 16; kk++) {
            float4 a0 = *(const float4*)&sm.p.Ws[cb][kk][ty * 8];
            float4 a1 = *(const float4*)&sm.p.Ws[cb][kk][ty * 8 + 4];
            ulonglong2 b0 = *(const ulonglong2*)&sm.p.Xs[cb][kk][tx * 8];
            ulonglong2 b1 = *(const ulonglong2*)&sm.p.Xs[cb][kk][tx * 8 + 4];
            ull bp[4] = {b0.x, b0.y, b1.x, b1.y};
            float aa[8] = {a0.x, a0.y, a0.z, a0.w, a1.x, a1.y, a1.z, a1.w};
#pragma unroll
            for (int i = 0; i < 8; i++) {
                ull ad = dup2(aa[i]);
#pragma unroll
                for (int j = 0; j < 4; j++) acc[i][j] = ffma2(ad, bp[j], acc[i][j]);
            }
        }
        if (ch < 15) {
            int nb = cb ^ 1;
#pragma unroll
            for (int u = 0; u < 2; u++) {
                sm.p.Ws[nb][wkg + u * 4 + 0][wrow] = (&wpre[u].x)[0];
                sm.p.Ws[nb][wkg + u * 4 + 1][wrow] = (&wpre[u].x)[1];
                sm.p.Ws[nb][wkg + u * 4 + 2][wrow] = (&wpre[u].x)[2];
                sm.p.Ws[nb][wkg + u * 4 + 3][wrow] = (&wpre[u].x)[3];
            }
#pragma unroll
            for (int u = 0; u < 4; u++)
                *(float4*)&sm.p.Xs[nb][xkk][xsg + u * 4] = xpre[u];
        }
        __syncthreads();
    }

#pragma unroll
    for (int i = 0; i < 8; i++) {
        ulonglong2 u0, u1;
        u0.x = acc[i][0]; u0.y = acc[i][1];
        u1.x = acc[i][2]; u1.y = acc[i][3];
        *(ulonglong2*)&sm.Cs[ty * 8 + i][tx * 8] = u0;
        *(ulonglong2*)&sm.Cs[ty * 8 + i][tx * 8 + 4] = u1;
    }
    __syncthreads();

    if (ot == 0) {
#pragma unroll
        for (int i = 0; i < 8; i++) {
            int o = i * 4 + (t >> 5);
            int sp = (t & 31) * 4;
            float4 v = *(const float4*)&sm.Cs[o][sp];
            float bb = qb[o];
            v.x += bb; v.y += bb; v.z += bb; v.w += bb;
            *(float4*)(g_q + (size_t)b * C8 * Sn + (size_t)o * Sn + s0 + sp) = v;
        }
        {
            int o = 32 + (t >> 2);
            int qcb = (t & 3) * 8;
            float bb = kb[o - 32];
            float* dst = g_k + (size_t)b * C8 * Dn + (size_t)(o - 32) * Dn + st * 32;
#pragma unroll
            for (int jj = 0; jj < 8; jj++) {
                int qc = qcb + jj;
                float m = fmaxf(fmaxf(sm.Cs[o][2 * qc], sm.Cs[o][2 * qc + 1]),
                                fmaxf(sm.Cs[o][64 + 2 * qc], sm.Cs[o][64 + 2 * qc + 1]));
                dst[qc] = m + bb;
            }
        }
    } else {
        int vg0 = (ot - 1) * 64;
        int o = t >> 1;
        int qcb = (t & 1) * 16;
        float bb = vb[vg0 + o];
        float* dst = g_v + (size_t)b * C2 * Dn + (size_t)(vg0 + o) * Dn + st * 32;
#pragma unroll
        for (int jj = 0; jj < 16; jj++) {
            int qc = qcb + jj;
            float m = fmaxf(fmaxf(sm.Cs[o][2 * qc], sm.Cs[o][2 * qc + 1]),
                            fmaxf(sm.Cs[o][64 + 2 * qc], sm.Cs[o][64 + 2 * qc + 1]));
            dst[qc] = m + bb;
        }
    }
}

// ---------------------------------------------------------------------------
// attn logits (unchanged)
// ---------------------------------------------------------------------------
__global__ __launch_bounds__(256) void attn_gemm_k() {
    int b = blockIdx.z, l0 = blockIdx.y * 128, j0 = blockIdx.x * 128;
    __shared__ __align__(16) float As[32][132];
    __shared__ __align__(16) float Bs[32][128];
    int t = threadIdx.x;
    int row = t >> 1, kg = (t & 1) * 16;
    const float* ar = g_q + (size_t)b * C8 * Sn + (size_t)(l0 + row) * 32 + kg;
    const float* br = g_k + (size_t)b * C8 * Dn + (size_t)(j0 + row) * 32 + kg;
#pragma unroll
    for (int u = 0; u < 4; u++) {
        float4 v = *(const float4*)(ar + u * 4);
        As[kg + u * 4 + 0][row] = v.x;
        As[kg + u * 4 + 1][row] = v.y;
        As[kg + u * 4 + 2][row] = v.z;
        As[kg + u * 4 + 3][row] = v.w;
        float4 w = *(const float4*)(br + u * 4);
        Bs[kg + u * 4 + 0][row] = w.x;
        Bs[kg + u * 4 + 1][row] = w.y;
        Bs[kg + u * 4 + 2][row] = w.z;
        Bs[kg + u * 4 + 3][row] = w.w;
    }
    __syncthreads();

    int ty = t >> 4, tx = t & 15;
    ull acc[8][4];
#pragma unroll
    for (int i = 0; i < 8; i++)
#pragma unroll
        for (int j = 0; j < 4; j++) acc[i][j] = 0ULL;

#pragma unroll
    for (int kk = 0; kk < 32; kk++) {
        float4 a0 = *(const float4*)&As[kk][ty * 8];
        float4 a1 = *(const float4*)&As[kk][ty * 8 + 4];
        ulonglong2 b0 = *(const ulonglong2*)&Bs[kk][tx * 8];
        ulonglong2 b1 = *(const ulonglong2*)&Bs[kk][tx * 8 + 4];
        ull bp[4] = {b0.x, b0.y, b1.x, b1.y};
        float aa[8] = {a0.x, a0.y, a0.z, a0.w, a1.x, a1.y, a1.z, a1.w};
#pragma unroll
        for (int i = 0; i < 8; i++) {
            ull ad = dup2(aa[i]);
#pragma unroll
            for (int j = 0; j < 4; j++) acc[i][j] = ffma2(ad, bp[j], acc[i][j]);
        }
    }

#pragma unroll
    for (int i = 0; i < 8; i++) {
        float* cr = g_attn + (size_t)b * Sn * Dn + (size_t)(l0 + ty * 8 + i) * Dn + j0 + tx * 8;
        ulonglong2 u0, u1;
        u0.x = acc[i][0]; u0.y = acc[i][1];
        u1.x = acc[i][2]; u1.y = acc[i][3];
        *(ulonglong2*)cr = u0;
        *(ulonglong2*)(cr + 4) = u1;
    }
}

// ---------------------------------------------------------------------------
// column softmax stats (unchanged)
// ---------------------------------------------------------------------------
__global__ void stats_k() {
    int b = blockIdx.y;
    int tx = threadIdx.x;
    int ty = threadIdx.y;
    int j = blockIdx.x * 128 + tx;
    const float* col = g_attn + (size_t)b * Sn * Dn + (size_t)ty * 1024 * Dn + j;

    float m = -1e30f, s = 0.f;
    for (int r = 0; r < 1024; r += 4) {
        float v0 = col[(size_t)(r + 0) * Dn];
        float v1 = col[(size_t)(r + 1) * Dn];
        float v2 = col[(size_t)(r + 2) * Dn];
        float v3 = col[(size_t)(r + 3) * Dn];
#define UPD(vv) { float mn_ = fmaxf(m, (vv)); s = fmaf(s, __expf(m - mn_), __expf((vv) - mn_)); m = mn_; }
        UPD(v0) UPD(v1) UPD(v2) UPD(v3)
#undef UPD
    }

    __shared__ float smx[4][128], ssum[4][128];
    smx[ty][tx] = m;
    ssum[ty][tx] = s;
    __syncthreads();
    if (ty == 0) {
#pragma unroll
        for (int tt = 1; tt < 4; tt++) {
            float m2 = smx[tt][tx], s2 = ssum[tt][tx];
            float mn = fmaxf(m, m2);
            s = s * __expf(m - mn) + s2 * __expf(m2 - mn);
            m = mn;
        }
        g_cmax[b * Dn + j] = m;
        g_crs[b * Dn + j] = 1.f / s;
    }
}

// ---------------------------------------------------------------------------
// applied GEMM via split-bf16 HMMA (mma.sync m16n8k16):
//   app[128l x 128c] = sum_j exp(attn[l,j]-cmax[j]) * (crs[j]*v[j,c])
// Each fp32 operand = hi_bf16 + lo_bf16; 3 MMA products (hh, hl, lh), fp32 acc.
// 256 thr = 8 warps (4l x 2c), warp tile 32l x 64c, K chunks of 16, dbl-buf.
// grid (Sn/128, Bn)
// ---------------------------------------------------------------------------
__global__ __launch_bounds__(256) void applied_hmma_k() {
    __shared__ __align__(16) unsigned short Ah[2][128][24];  // 48B rows (16 k + pad)
    __shared__ __align__(16) unsigned short Al[2][128][24];
    __shared__ __align__(16) unsigned short Bh[2][16][136];  // 272B rows (128 c + pad)
    __shared__ __align__(16) unsigned short Bl[2][16][136];

    int t = threadIdx.x, lane = t & 31, wid = t >> 5;
    int b = blockIdx.y, l0 = blockIdx.x * 128;

    // loader maps
    int arow = t >> 1, ak = (t & 1) * 8;
    const float* abase = g_attn + (size_t)b * Sn * Dn + (size_t)(l0 + arow) * Dn + ak;
    const float* cmb = g_cmax + b * Dn + ak;
    int bj = t >> 4, bc = (t & 15) * 8;
    const float* vbase = g_v + (size_t)b * C2 * Dn;  // [j*128 + c]
    const float* crb = g_crs + b * Dn;

    // mma maps
    int wl = wid >> 1, wc = wid & 1;
    uint32_t a_off = (uint32_t)((wl * 32 + (lane & 7) + ((lane >> 3) & 1) * 8) * 48 +
                                ((lane >> 4) * 8) * 2);
    uint32_t b_off = (uint32_t)(((lane & 7) + ((lane >> 3) & 1) * 8) * 272 +
                                (wc * 64 + (lane >> 4) * 8) * 2);

    float acc[2][8][4];
#pragma unroll
    for (int i = 0; i < 2; i++)
#pragma unroll
        for (int n = 0; n < 8; n++)
#pragma unroll
            for (int q = 0; q < 4; q++) acc[i][n][q] = 0.f;

    // ---- load + convert chunk 0 ----
    {
        float4 av0 = *(const float4*)(abase);
        float4 av1 = *(const float4*)(abase + 4);
        float4 m0 = *(const float4*)(cmb);
        float4 m1 = *(const float4*)(cmb + 4);
        float p[8] = {__expf(av0.x - m0.x), __expf(av0.y - m0.y),
                      __expf(av0.z - m0.z), __expf(av0.w - m0.w),
                      __expf(av1.x - m1.x), __expf(av1.y - m1.y),
                      __expf(av1.z - m1.z), __expf(av1.w - m1.w)};
        uint h[4], l[4];
#pragma unroll
        for (int i = 0; i < 4; i++) split2(p[2 * i], p[2 * i + 1], h[i], l[i]);
        *(uint4*)&Ah[0][arow][ak] = make_uint4(h[0], h[1], h[2], h[3]);
        *(uint4*)&Al[0][arow][ak] = make_uint4(l[0], l[1], l[2], l[3]);

        float sc = crb[bj];
        const float* vp = vbase + (size_t)bj * C2 + bc;
        float4 bv0 = *(const float4*)(vp);
        float4 bv1 = *(const float4*)(vp + 4);
        float q[8] = {bv0.x * sc, bv0.y * sc, bv0.z * sc, bv0.w * sc,
                      bv1.x * sc, bv1.y * sc, bv1.z * sc, bv1.w * sc};
#pragma unroll
        for (int i = 0; i < 4; i++) split2(q[2 * i], q[2 * i + 1], h[i], l[i]);
        *(uint4*)&Bh[0][bj][bc] = make_uint4(h[0], h[1], h[2], h[3]);
        *(uint4*)&Bl[0][bj][bc] = make_uint4(l[0], l[1], l[2], l[3]);
    }
    __syncthreads();

    for (int ch = 0; ch < 64; ch++) {
        int buf = ch & 1;
        float pa[8], qb2[8];
        if (ch < 63) {
            const float* ap = abase + (ch + 1) * 16;
            float4 av0 = *(const float4*)(ap);
            float4 av1 = *(const float4*)(ap + 4);
            const float* cp = cmb + (ch + 1) * 16;
            float4 m0 = *(const float4*)(cp);
            float4 m1 = *(const float4*)(cp + 4);
            pa[0] = __expf(av0.x - m0.x); pa[1] = __expf(av0.y - m0.y);
            pa[2] = __expf(av0.z - m0.z); pa[3] = __expf(av0.w - m0.w);
            pa[4] = __expf(av1.x - m1.x); pa[5] = __expf(av1.y - m1.y);
            pa[6] = __expf(av1.z - m1.z); pa[7] = __expf(av1.w - m1.w);
            int j = (ch + 1) * 16 + bj;
            float sc = crb[j];
            const float* vp = vbase + (size_t)j * C2 + bc;
            float4 bv0 = *(const float4*)(vp);
            float4 bv1 = *(const float4*)(vp + 4);
            qb2[0] = bv0.x * sc; qb2[1] = bv0.y * sc; qb2[2] = bv0.z * sc; qb2[3] = bv0.w * sc;
            qb2[4] = bv1.x * sc; qb2[5] = bv1.y * sc; qb2[6] = bv1.z * sc; qb2[7] = bv1.w * sc;
        }

        // ---- MMA on buf ----
        {
            uint32_t ah_base = smem_u32(&Ah[buf][0][0]) + a_off;
            uint32_t al_base = smem_u32(&Al[buf][0][0]) + a_off;
            uint32_t bh_base = smem_u32(&Bh[buf][0][0]) + b_off;
            uint32_t bl_base = smem_u32(&Bl[buf][0][0]) + b_off;

            uint ah[2][4], al2[2][4];
#pragma unroll
            for (int ln = 0; ln < 2; ln++) {
                ldsm4(ah_base + ln * 16 * 48, ah[ln][0], ah[ln][1], ah[ln][2], ah[ln][3]);
                ldsm4(al_base + ln * 16 * 48, al2[ln][0], al2[ln][1], al2[ln][2], al2[ln][3]);
            }
#pragma unroll
            for (int nn = 0; nn < 4; nn++) {
                uint bh0, bh1, bh2, bh3, bl0, bl1, bl2, bl3;
                ldsm4t(bh_base + nn * 32, bh0, bh1, bh2, bh3);
                ldsm4t(bl_base + nn * 32, bl0, bl1, bl2, bl3);
#pragma unroll
                for (int ln = 0; ln < 2; ln++) {
                    // n-tile 2*nn
                    mma16816(acc[ln][2 * nn], ah[ln][0], ah[ln][1], ah[ln][2], ah[ln][3], bh0, bh1);
                    mma16816(acc[ln][2 * nn], ah[ln][0], ah[ln][1], ah[ln][2], ah[ln][3], bl0, bl1);
                    mma16816(acc[ln][2 * nn], al2[ln][0], al2[ln][1], al2[ln][2], al2[ln][3], bh0, bh1);
                    // n-tile 2*nn+1
                    mma16816(acc[ln][2 * nn + 1], ah[ln][0], ah[ln][1], ah[ln][2], ah[ln][3], bh2, bh3);
                    mma16816(acc[ln][2 * nn + 1], ah[ln][0], ah[ln][1], ah[ln][2], ah[ln][3], bl2, bl3);
                    mma16816(acc[ln][2 * nn + 1], al2[ln][0], al2[ln][1], al2[ln][2], al2[ln][3], bh2, bh3);
                }
            }
        }

        // ---- store converted chunk ch+1 into other buf ----
        if (ch < 63) {
            int nb = buf ^ 1;
            uint h[4], l[4];
#pragma unroll
            for (int i = 0; i < 4; i++) split2(pa[2 * i], pa[2 * i + 1], h[i], l[i]);
            *(uint4*)&Ah[nb][arow][ak] = make_uint4(h[0], h[1], h[2], h[3]);
            *(uint4*)&Al[nb][arow][ak] = make_uint4(l[0], l[1], l[2], l[3]);
#pragma unroll
            for (int i = 0; i < 4; i++) split2(qb2[2 * i], qb2[2 * i + 1], h[i], l[i]);
            *(uint4*)&Bh[nb][bj][bc] = make_uint4(h[0], h[1], h[2], h[3]);
            *(uint4*)&Bl[nb][bj][bc] = make_uint4(l[0], l[1], l[2], l[3]);
        }
        __syncthreads();
    }

    // ---- epilogue ----
    float* ob = g_app + (size_t)b * Sn * C2;
#pragma unroll
    for (int ln = 0; ln < 2; ln++) {
        int r0 = l0 + wl * 32 + ln * 16 + (lane >> 2);
#pragma unroll
        for (int n = 0; n < 8; n++) {
            int c = wc * 64 + n * 8 + (lane & 3) * 2;
            float2 d0 = make_float2(acc[ln][n][0], acc[ln][n][1]);
            float2 d1 = make_float2(acc[ln][n][2], acc[ln][n][3]);
            *(float2*)(ob + (size_t)r0 * C2 + c) = d0;
            *(float2*)(ob + (size_t)(r0 + 8) * C2 + c) = d1;
        }
    }
}

// ---------------------------------------------------------------------------
// output conv + residual (unchanged)
// ---------------------------------------------------------------------------
__global__ __launch_bounds__(256) void out_conv_k(
    const float* __restrict__ x, const float* __restrict__ w2,
    const float* __restrict__ b2, const float* __restrict__ gamma,
    float* __restrict__ out) {
    int b = blockIdx.z, o0 = blockIdx.y * 128, sp0 = blockIdx.x * 128;
    __shared__ __align__(16) float Ws[2][16][132];
    __shared__ __align__(16) float Bs[2][16][128];
    int t = threadIdx.x;

    int wrow = t >> 1, wkg = (t & 1) * 8;
    const float* wsrc = w2 + (size_t)(o0 + wrow) * C2 + wkg;
    int bkk = t >> 4, bsg = (t & 15) * 8;
    const float* asrc = g_app + (size_t)b * Sn * C2 + (size_t)bkk * Sn + sp0 + bsg;

    int ty = t >> 4, tx = t & 15;
    ull acc[8][4];
#pragma unroll
    for (int i = 0; i < 8; i++)
#pragma unroll
        for (int j = 0; j < 4; j++) acc[i][j] = 0ULL;

    {
        float4 w0 = *(const float4*)(wsrc);
        float4 w1 = *(const float4*)(wsrc + 4);
        Ws[0][wkg + 0][wrow] = w0.x; Ws[0][wkg + 1][wrow] = w0.y;
        Ws[0][wkg + 2][wrow] = w0.z; Ws[0][wkg + 3][wrow] = w0.w;
        Ws[0][wkg + 4][wrow] = w1.x; Ws[0][wkg + 5][wrow] = w1.y;
        Ws[0][wkg + 6][wrow] = w1.z; Ws[0][wkg + 7][wrow] = w1.w;
        *(float4*)&Bs[0][bkk][bsg] = *(const float4*)(asrc);
        *(float4*)&Bs[0][bkk][bsg + 4] = *(const float4*)(asrc + 4);
    }
    __syncthreads();

    for (int ch = 0; ch < 8; ch++) {
        int cb = ch & 1;
        float4 w0, w1, pb0, pb1;
        if (ch < 7) {
            int kc = (ch + 1) * 16;
            w0 = *(const float4*)(wsrc + kc);
            w1 = *(const float4*)(wsrc + kc + 4);
            const float* ap = asrc + (size_t)kc * Sn;
            pb0 = *(const float4*)(ap);
            pb1 = *(const float4*)(ap + 4);
        }
#pragma unroll
        for (int kk = 0; kk < 16; kk++) {
            float4 a0 = *(const float4*)&Ws[cb][kk][ty * 8];
            float4 a1 = *(const float4*)&Ws[cb][kk][ty * 8 + 4];
            ulonglong2 b0 = *(const ulonglong2*)&Bs[cb][kk][tx * 8];
            ulonglong2 b1 = *(const ulonglong2*)&Bs[cb][kk][tx * 8 + 4];
            ull bp[4] = {b0.x, b0.y, b1.x, b1.y};
            float aa[8] = {a0.x, a0.y, a0.z, a0.w, a1.x, a1.y, a1.z, a1.w};
#pragma unroll
            for (int i = 0; i < 8; i++) {
                ull ad = dup2(aa[i]);
#pragma unroll
                for (int j = 0; j < 4; j++) acc[i][j] = ffma2(ad, bp[j], acc[i][j]);
            }
        }
        if (ch < 7) {
            int nb = cb ^ 1;
            Ws[nb][wkg + 0][wrow] = w0.x; Ws[nb][wkg + 1][wrow] = w0.y;
            Ws[nb][wkg + 2][wrow] = w0.z; Ws[nb][wkg + 3][wrow] = w0.w;
            Ws[nb][wkg + 4][wrow] = w1.x; Ws[nb][wkg + 5][wrow] = w1.y;
            Ws[nb][wkg + 6][wrow] = w1.z; Ws[nb][wkg + 7][wrow] = w1.w;
            *(float4*)&Bs[nb][bkk][bsg] = pb0;
            *(float4*)&Bs[nb][bkk][bsg + 4] = pb1;
        }
        __syncthreads();
    }

    float g = gamma[0];
#pragma unroll
    for (int i = 0; i < 8; i++) {
        int o = o0 + ty * 8 + i;
        float bb = b2[o];
        const float* xr = x + (size_t)b * Cc * Sn + (size_t)o * Sn + sp0 + tx * 8;
        float* orow = out + (size_t)b * Cc * Sn + (size_t)o * Sn + sp0 + tx * 8;
        float2 v0 = upk(acc[i][0]), v1 = upk(acc[i][1]);
        float2 v2 = upk(acc[i][2]), v3 = upk(acc[i][3]);
        float4 xa = *(const float4*)(xr);
        float4 xb4 = *(const float4*)(xr + 4);
        float4 r0, r1;
        r0.x = fmaf(g, v0.x + bb, xa.x);
        r0.y = fmaf(g, v0.y + bb, xa.y);
        r0.z = fmaf(g, v1.x + bb, xa.z);
        r0.w = fmaf(g, v1.y + bb, xa.w);
        r1.x = fmaf(g, v2.x + bb, xb4.x);
        r1.y = fmaf(g, v2.y + bb, xb4.y);
        r1.z = fmaf(g, v3.x + bb, xb4.z);
        r1.w = fmaf(g, v3.y + bb, xb4.w);
        *(float4*)(orow) = r0;
        *(float4*)(orow + 4) = r1;
    }
}

// ---------------------------------------------------------------------------
extern "C" void kernel_launch(void* const* d_in, const int* in_sizes, int n_in,
                              void* d_out, int out_size) {
    const float* x   = (const float*)d_in[0];
    const float* qw  = (const float*)d_in[1];
    const float* qb  = (const float*)d_in[2];
    const float* kw  = (const float*)d_in[3];
    const float* kb  = (const float*)d_in[4];
    const float* vw  = (const float*)d_in[5];
    const float* vb  = (const float*)d_in[6];
    const float* v2w = (const float*)d_in[7];
    const float* v2b = (const float*)d_in[8];
    const float* gm  = (const float*)d_in[9];
    float* out = (float*)d_out;

    conv_all_k<<<dim3(32, 3, Bn), 128>>>(x, qw, qb, kw, kb, vw, vb);
    attn_gemm_k<<<dim3(Dn / 128, Sn / 128, Bn), 256>>>();
    stats_k<<<dim3(Dn / 128, Bn), dim3(128, 4)>>>();
    applied_hmma_k<<<dim3(Sn / 128, Bn), 256>>>();
    out_conv_k<<<dim3(Sn / 128, 2, Bn), 256>>>(x, v2w, v2b, gm, out);
}